// round 13
// baseline (speedup 1.0000x reference)
#include <cuda_runtime.h>
#include <cuda_fp16.h>
#include <cstdint>

// ============================================================================
// Problem constants
// ============================================================================
#define B_DIM   256
#define T_DIM   2048
#define K_DIM   64
#define H_DIM   128
#define TILE_T  32
#define N_TILES (T_DIM / TILE_T)   // 64

// Scan: y_t = 0.9*y_{t-1} - 1.25*th_{t-1} + g_t, th = tanh(y), spk = .5th+.5
// g = 2.5*ff - 1.5  (2.5 folded into W, bias' = 2.5b - 1.5)
// GEMM: 2-term fp16 split  ff ~= wh*xh + wh*xl,  xl = fp16(x - xh)

// ============================================================================
// SMEM layout (bytes) — 82944 total (2 CTAs/SM)
//   [0, 27648)       x ring: 3 slots x 9216 (fp16 hi 4608 + fp16 lo 4608)
//   [27648, 82944)   ff ring: 3 slots x 18432 ([h][t] stride 36 floats)
//   W_hi (init only) aliases ff region at 27648 (128 x 144 B = 18432).
// ============================================================================
#define WSTR      72
#define ROWB      144
#define XBUF(s)   ((s) * 9216)
#define SMEM_FF   27648
#define FFB(s)    (SMEM_FF + (s) * 18432)
#define FF_STR    36                   // floats per head row (conflict-free)
#define SMEM_W_HI 27648
#define SMEM_TOTAL 82944

// Named barriers (256 threads = 128 producers + 128 consumers):
//   FFREADY(s)=1+s, FFFREE(s)=4+s, XREADY(s)=7+s, XFREE(s)=10+s,
//   13 = producer-only (128) W_hi hoist guard
#define BAR_SYNC(id)   asm volatile("bar.sync %0, 256;"   :: "r"(id) : "memory")
#define BAR_ARRIVE(id) asm volatile("bar.arrive %0, 256;" :: "r"(id) : "memory")

// ============================================================================
// Helpers
// ============================================================================
__device__ __forceinline__ uint32_t smem_to_u32(const void* p) {
    uint32_t a;
    asm("{ .reg .u64 t; cvta.to.shared.u64 t, %1; cvt.u32.u64 %0, t; }"
        : "=r"(a) : "l"(p));
    return a;
}
__device__ __forceinline__ float tanhf_approx(float x) {
    float y; asm("tanh.approx.f32 %0, %1;" : "=f"(y) : "f"(x)); return y;
}
__device__ __forceinline__ void ldm_x4(uint32_t* r, uint32_t addr) {
    asm volatile("ldmatrix.sync.aligned.m8n8.x4.shared.b16 {%0,%1,%2,%3}, [%4];"
        : "=r"(r[0]), "=r"(r[1]), "=r"(r[2]), "=r"(r[3]) : "r"(addr));
}
__device__ __forceinline__ void mma_f16(float* d, const uint32_t* a, const uint32_t* b) {
    asm volatile(
        "mma.sync.aligned.m16n8k16.row.col.f32.f16.f16.f32 "
        "{%0,%1,%2,%3},{%4,%5,%6,%7},{%8,%9},{%0,%1,%2,%3};"
        : "+f"(d[0]), "+f"(d[1]), "+f"(d[2]), "+f"(d[3])
        : "r"(a[0]), "r"(a[1]), "r"(a[2]), "r"(a[3]), "r"(b[0]), "r"(b[1]));
}
__device__ __forceinline__ uint32_t pack_h2(__half a, __half b) {
    return ((uint32_t)__half_as_ushort(b) << 16) | __half_as_ushort(a);
}
// fp16 2-term split: hi = fp16(v), lo = fp16(v - hi)
__device__ __forceinline__ void cvt_pack_f16(float4 v, uint2& hi, uint2& lo) {
    __half h0 = __float2half_rn(v.x);
    __half h1 = __float2half_rn(v.y);
    __half h2 = __float2half_rn(v.z);
    __half h3 = __float2half_rn(v.w);
    __half l0 = __float2half_rn(v.x - __half2float(h0));
    __half l1 = __float2half_rn(v.y - __half2float(h1));
    __half l2 = __float2half_rn(v.z - __half2float(h2));
    __half l3 = __float2half_rn(v.w - __half2float(h3));
    hi.x = pack_h2(h0, h1); hi.y = pack_h2(h2, h3);
    lo.x = pack_h2(l0, l1); lo.y = pack_h2(l2, l3);
}
// full-slot convert (prologue only)
__device__ __forceinline__ void convert_to_slot(char* smem, int s, int ct,
                                                const float4* xr) {
#pragma unroll
    for (int q = 0; q < 4; ++q) {
        int idx = ct + (q << 7);
        int row = idx >> 4, c4 = idx & 15;
        uint32_t off = (uint32_t)row * ROWB + c4 * 8;
        uint2 hi, lo; cvt_pack_f16(xr[q], hi, lo);
        *reinterpret_cast<uint2*>(smem + XBUF(s) + off)        = hi;
        *reinterpret_cast<uint2*>(smem + XBUF(s) + 4608 + off) = lo;
    }
}

// ============================================================================
// Warp-specialized kernel (R12 skeleton + consumer diet). 256 threads/CTA.
//   tid 0..127  : consumers — tanh scan (thread = head); x convert spliced
//                 into the scan's MUFU stall shadow; ff via 8x LDS.128
//   tid 128..255: producers — 2-term fp16 GEMM (A in regs, 64 HMMA/tile),
//                 ff stored [h][t] via STS.64
// ============================================================================
__global__ void __launch_bounds__(256, 2)
snn_encoder_kernel(const float* __restrict__ x, const float* __restrict__ W,
                   const float* __restrict__ bvec, float* __restrict__ out) {
    extern __shared__ char smem[];
    const uint32_t sb = smem_to_u32(smem);
    const int tid = threadIdx.x;
    const int b   = blockIdx.x;
    const float* xb = x + (size_t)b * T_DIM * K_DIM;

    // ---- Cooperative W convert: (2.5*W) fp32 -> fp16 hi only (aliases ff)
    {
        const float4* w4 = reinterpret_cast<const float4*>(W);
#pragma unroll
        for (int q = 0; q < 8; ++q) {
            int idx = tid + (q << 8);            // 2048 float4
            float4 v = __ldg(&w4[idx]);
            v.x *= 2.5f; v.y *= 2.5f; v.z *= 2.5f; v.w *= 2.5f;
            int row = idx >> 4, c4 = idx & 15;
            uint32_t off = (uint32_t)row * ROWB + c4 * 8;
            __half h0 = __float2half_rn(v.x);
            __half h1 = __float2half_rn(v.y);
            __half h2 = __float2half_rn(v.z);
            __half h3 = __float2half_rn(v.w);
            uint2 hi;
            hi.x = pack_h2(h0, h1); hi.y = pack_h2(h2, h3);
            *reinterpret_cast<uint2*>(smem + SMEM_W_HI + off) = hi;
        }
    }
    __syncthreads();

    if (tid >= 128) {
        // ==================== PRODUCERS ====================
        const int pt   = tid - 128;
        const int lane = pt & 31;
        const int pw   = pt >> 5;                // heads [32pw, 32pw+32)
        const int j    = lane >> 3;

        const uint32_t a_off = (uint32_t)(((j & 1) * 8 + (lane & 7)) * WSTR + ((j >> 1) * 8)) * 2;
        const uint32_t b_off = (uint32_t)(((j >> 1) * 8 + (lane & 7)) * WSTR + ((j & 1) * 8)) * 2;

        // hoist W_hi fragments into registers (ff ring aliases W_hi after)
        uint32_t Ahi[2][4][4];
        {
            const uint32_t aW_hi = sb + SMEM_W_HI + (uint32_t)(pw * 32) * ROWB + a_off;
#pragma unroll
            for (int mt = 0; mt < 2; ++mt)
#pragma unroll
                for (int ks = 0; ks < 4; ++ks)
                    ldm_x4(Ahi[mt][ks], aW_hi + (uint32_t)mt * 16 * ROWB + ks * 32);
        }
        asm volatile("bar.sync 13, 128;" ::: "memory");

        // bias' = 2.5*b - 1.5 folded into accumulator init
        const int r0 = lane >> 2;
        const int c0 = 2 * (lane & 3);
        float bias0[2], bias1[2];
#pragma unroll
        for (int mt = 0; mt < 2; ++mt) {
            bias0[mt] = fmaf(__ldg(&bvec[pw * 32 + mt * 16 + r0]), 2.5f, -1.5f);
            bias1[mt] = fmaf(__ldg(&bvec[pw * 32 + mt * 16 + r0 + 8]), 2.5f, -1.5f);
        }

        int sx = 0, sf = 0;
        for (int i = 0; i < N_TILES; ++i) {
            BAR_SYNC(7 + sx);                    // wait x tile i converted

            float d[2][4][4];
#pragma unroll
            for (int mt = 0; mt < 2; ++mt)
#pragma unroll
                for (int nt = 0; nt < 4; ++nt) {
                    d[mt][nt][0] = bias0[mt]; d[mt][nt][1] = bias0[mt];
                    d[mt][nt][2] = bias1[mt]; d[mt][nt][3] = bias1[mt];
                }
            const uint32_t bX_hi = sb + XBUF(sx) + b_off;
            const uint32_t bX_lo = bX_hi + 4608;
#pragma unroll
            for (int ks = 0; ks < 4; ++ks) {
                uint32_t bh[2][4], bl[2][4];
                ldm_x4(bh[0], bX_hi + ks * 32);
                ldm_x4(bh[1], bX_hi + 16 * ROWB + ks * 32);
                ldm_x4(bl[0], bX_lo + ks * 32);
                ldm_x4(bl[1], bX_lo + 16 * ROWB + ks * 32);
#pragma unroll
                for (int mt = 0; mt < 2; ++mt)
#pragma unroll
                    for (int nt = 0; nt < 4; ++nt) {
                        const uint32_t* bhp = &bh[nt >> 1][(nt & 1) * 2];
                        const uint32_t* blp = &bl[nt >> 1][(nt & 1) * 2];
                        mma_f16(d[mt][nt], Ahi[mt][ks], bhp);   // wh * xh
                        mma_f16(d[mt][nt], Ahi[mt][ks], blp);   // wh * xl
                    }
            }
            BAR_ARRIVE(10 + sx);                 // x slot free (LDSM done)

            if (i >= 3) BAR_SYNC(4 + sf);        // wait ff slot free

            // store ff tile, layout [h][t] stride 36, STS.64 pairs
            {
                float* ffp = reinterpret_cast<float*>(smem + FFB(sf));
                const int baser = pw * 32 + r0;
#pragma unroll
                for (int mt = 0; mt < 2; ++mt) {
                    const int row = baser + mt * 16;
#pragma unroll
                    for (int nt = 0; nt < 4; ++nt) {
                        const int col = nt * 8 + c0;
                        *reinterpret_cast<float2*>(ffp + row * FF_STR + col) =
                            make_float2(d[mt][nt][0], d[mt][nt][1]);
                        *reinterpret_cast<float2*>(ffp + (row + 8) * FF_STR + col) =
                            make_float2(d[mt][nt][2], d[mt][nt][3]);
                    }
                }
            }
            BAR_ARRIVE(1 + sf);                  // ff tile ready

            if (++sx == 3) sx = 0;
            if (++sf == 3) sf = 0;
        }
    } else {
        // ==================== CONSUMERS (scan + spliced x feed) ============
        const int h  = tid;
        const int ct = tid;
        float* outp = out + (size_t)b * T_DIM * H_DIM + h;

        // prologue: convert x tiles 0,1 into slots 0,1; prefetch tile 2
        float4 xr[4];
        {
            const float4* x4 = reinterpret_cast<const float4*>(xb);
#pragma unroll
            for (int q = 0; q < 4; ++q) xr[q] = __ldg(&x4[ct + (q << 7)]);
            convert_to_slot(smem, 0, ct, xr);
            BAR_ARRIVE(7 + 0);
            x4 = reinterpret_cast<const float4*>(xb + (size_t)TILE_T * K_DIM);
#pragma unroll
            for (int q = 0; q < 4; ++q) xr[q] = __ldg(&x4[ct + (q << 7)]);
            convert_to_slot(smem, 1, ct, xr);
            BAR_ARRIVE(7 + 1);
            x4 = reinterpret_cast<const float4*>(xb + (size_t)2 * TILE_T * K_DIM);
#pragma unroll
            for (int q = 0; q < 4; ++q) xr[q] = __ldg(&x4[ct + (q << 7)]);
        }

        // scan state: z = 0.9*y_{-1} - 1.25*th_{-1} = -1.0 (mem=0, spk=0)
        float z = -1.0f;
        int sf = 0, sx = 2;                      // next convert slot = tile 2

        for (int i = 0; i < N_TILES; ++i) {
            const bool cvt = (i + 2 < N_TILES);

            BAR_SYNC(1 + sf);                    // wait ff tile i
            const float* fp = reinterpret_cast<const float*>(smem + FFB(sf))
                              + h * FF_STR;
            float4 g4[8];                        // 8x LDS.128, conflict-free
#pragma unroll
            for (int q = 0; q < 8; ++q)
                g4[q] = *reinterpret_cast<const float4*>(fp + q * 4);
            BAR_ARRIVE(4 + sf);                  // free ff slot immediately
            if (++sf == 3) sf = 0;

            if (cvt && i + 2 >= 3) BAR_SYNC(10 + sx);   // x slot free

            const float* gf = reinterpret_cast<const float*>(g4);
            float* po = outp + (size_t)i * TILE_T * H_DIM;
            float y = z + gf[0];
            // scan with x-convert spliced into the MUFU stall shadow
#pragma unroll
            for (int ck = 0; ck < 4; ++ck) {
#pragma unroll
                for (int tt = 0; tt < 8; ++tt) {
                    const int t = ck * 8 + tt;
                    float th = tanhf_approx(y);        // MUFU (critical path)
                    float gn = (t < TILE_T - 1) ? gf[t + 1] : 0.0f;
                    float a  = fmaf(0.9f, y, gn);      // parallel with tanh
                    y = fmaf(th, -1.25f, a);           // y_{t+1} (z at t=31)
                    float spk = fmaf(th, 0.5f, 0.5f);  // off critical path
                    po[(size_t)t * H_DIM] = spk;
                }
                if (cvt) {                             // 1 float4 chunk / 8 steps
                    int idx = ct + (ck << 7);
                    int row = idx >> 4, c4 = idx & 15;
                    uint32_t off = (uint32_t)row * ROWB + c4 * 8;
                    uint2 hi, lo; cvt_pack_f16(xr[ck], hi, lo);
                    *reinterpret_cast<uint2*>(smem + XBUF(sx) + off)        = hi;
                    *reinterpret_cast<uint2*>(smem + XBUF(sx) + 4608 + off) = lo;
                }
            }
            z = y;

            if (cvt) {
                BAR_ARRIVE(7 + sx);              // x tile i+2 ready
                if (++sx == 3) sx = 0;
            }
            // prefetch x tile i+3 (xr regs now free)
            if (i + 3 < N_TILES) {
                const float4* x4 = reinterpret_cast<const float4*>(
                    xb + (size_t)(i + 3) * TILE_T * K_DIM);
#pragma unroll
                for (int q = 0; q < 4; ++q) xr[q] = __ldg(&x4[ct + (q << 7)]);
            }
        }
    }
}

// ============================================================================
// Launch. Inputs: x [256,2048,64] f32, W [128,64] f32, b [128] f32 -> out f32
// ============================================================================
extern "C" void kernel_launch(void* const* d_in, const int* in_sizes, int n_in,
                              void* d_out, int out_size) {
    const float* x = (const float*)d_in[0];
    const float* W = (const float*)d_in[1];
    const float* b = (const float*)d_in[2];
    float* out = (float*)d_out;

    cudaFuncSetAttribute(snn_encoder_kernel,
                         cudaFuncAttributeMaxDynamicSharedMemorySize, SMEM_TOTAL);
    snn_encoder_kernel<<<B_DIM, 256, SMEM_TOTAL>>>(x, W, b, out);
}

// round 14
// speedup vs baseline: 1.0769x; 1.0769x over previous
#include <cuda_runtime.h>
#include <cuda_fp16.h>
#include <cstdint>

// ============================================================================
// Problem constants
// ============================================================================
#define B_DIM   256
#define T_DIM   2048
#define K_DIM   64
#define H_DIM   128
#define TILE_T  64                     // 2 internal 32-step halves
#define N_TILES (T_DIM / TILE_T)       // 32

// Scan: y_t = 0.9*y_{t-1} - 1.25*th_{t-1} + g_t, th = tanh(y), spk = .5th+.5
// g = 2.5*ff - 1.5  (2.5 folded into W, bias' = 2.5b - 1.5)
// GEMM: 2-term fp16 split  ff ~= wh*xh + wh*xl,  xl = fp16(x - xh)

// ============================================================================
// SMEM layout (bytes) — 104448 total (2 CTAs/SM)
//   [0, 36864)        x ring: 2 slots x 18432 (fp16 hi 9216 + fp16 lo 9216),
//                     64 rows x 144 B per plane
//   [36864, 104448)   ff ring: 2 slots x 33792 ([t][h] stride 132 floats)
//   W_hi (init only) aliases ff region at 36864 (128 x 144 B = 18432).
// ============================================================================
#define WSTR      72
#define ROWB      144
#define XBUF(s)   ((s) * 18432)
#define XLO       9216
#define SMEM_FF   36864
#define FFB(s)    (SMEM_FF + (s) * 33792)
#define FF_STR    132
#define SMEM_W_HI 36864
#define SMEM_TOTAL 104448

// Named barriers (256 threads = 128 producers + 128 consumers):
//   FFREADY(s)=1+s, FFFREE(s)=3+s, XREADY(s)=5+s, XFREE(s)=7+s (s in {0,1})
//   13 = producer-only (128) W_hi hoist guard
#define BAR_SYNC(id)   asm volatile("bar.sync %0, 256;"   :: "r"(id) : "memory")
#define BAR_ARRIVE(id) asm volatile("bar.arrive %0, 256;" :: "r"(id) : "memory")

// ============================================================================
// Helpers
// ============================================================================
__device__ __forceinline__ uint32_t smem_to_u32(const void* p) {
    uint32_t a;
    asm("{ .reg .u64 t; cvta.to.shared.u64 t, %1; cvt.u32.u64 %0, t; }"
        : "=r"(a) : "l"(p));
    return a;
}
__device__ __forceinline__ float tanhf_approx(float x) {
    float y; asm("tanh.approx.f32 %0, %1;" : "=f"(y) : "f"(x)); return y;
}
__device__ __forceinline__ void ldm_x4(uint32_t* r, uint32_t addr) {
    asm volatile("ldmatrix.sync.aligned.m8n8.x4.shared.b16 {%0,%1,%2,%3}, [%4];"
        : "=r"(r[0]), "=r"(r[1]), "=r"(r[2]), "=r"(r[3]) : "r"(addr));
}
__device__ __forceinline__ void mma_f16(float* d, const uint32_t* a, const uint32_t* b) {
    asm volatile(
        "mma.sync.aligned.m16n8k16.row.col.f32.f16.f16.f32 "
        "{%0,%1,%2,%3},{%4,%5,%6,%7},{%8,%9},{%0,%1,%2,%3};"
        : "+f"(d[0]), "+f"(d[1]), "+f"(d[2]), "+f"(d[3])
        : "r"(a[0]), "r"(a[1]), "r"(a[2]), "r"(a[3]), "r"(b[0]), "r"(b[1]));
}
__device__ __forceinline__ uint32_t pack_h2(__half a, __half b) {
    return ((uint32_t)__half_as_ushort(b) << 16) | __half_as_ushort(a);
}
// fp16 2-term split: hi = fp16(v), lo = fp16(v - hi)
__device__ __forceinline__ void cvt_pack_f16(float4 v, uint2& hi, uint2& lo) {
    __half h0 = __float2half_rn(v.x);
    __half h1 = __float2half_rn(v.y);
    __half h2 = __float2half_rn(v.z);
    __half h3 = __float2half_rn(v.w);
    __half l0 = __float2half_rn(v.x - __half2float(h0));
    __half l1 = __float2half_rn(v.y - __half2float(h1));
    __half l2 = __float2half_rn(v.z - __half2float(h2));
    __half l3 = __float2half_rn(v.w - __half2float(h3));
    hi.x = pack_h2(h0, h1); hi.y = pack_h2(h2, h3);
    lo.x = pack_h2(l0, l1); lo.y = pack_h2(l2, l3);
}
// consumer-side: convert xr regs (8 float4 = this thread's share of a 64x64
// tile) into x ring slot s
__device__ __forceinline__ void convert_to_slot(char* smem, int s, int ct,
                                                const float4* xr) {
#pragma unroll
    for (int q = 0; q < 8; ++q) {
        int idx = ct + (q << 7);             // 0..1023 float4
        int row = idx >> 4, c4 = idx & 15;
        uint32_t off = (uint32_t)row * ROWB + c4 * 8;
        uint2 hi, lo; cvt_pack_f16(xr[q], hi, lo);
        *reinterpret_cast<uint2*>(smem + XBUF(s) + off)       = hi;
        *reinterpret_cast<uint2*>(smem + XBUF(s) + XLO + off) = lo;
    }
}

// ============================================================================
// Warp-specialized kernel (R12 protocol, 64-step tiles in 2 halves).
//   tid 0..127  : consumers — tanh scan (thread = head) + x load/convert
//                 (x-READY published BEFORE the scan — R13 lesson)
//   tid 128..255: producers — 2-term fp16 GEMM, 2 x 64 HMMA per round
// ============================================================================
__global__ void __launch_bounds__(256, 2)
snn_encoder_kernel(const float* __restrict__ x, const float* __restrict__ W,
                   const float* __restrict__ bvec, float* __restrict__ out) {
    extern __shared__ char smem[];
    const uint32_t sb = smem_to_u32(smem);
    const int tid = threadIdx.x;
    const int b   = blockIdx.x;
    const float* xb = x + (size_t)b * T_DIM * K_DIM;

    // ---- Cooperative W convert: (2.5*W) fp32 -> fp16 hi only (aliases ff)
    {
        const float4* w4 = reinterpret_cast<const float4*>(W);
#pragma unroll
        for (int q = 0; q < 8; ++q) {
            int idx = tid + (q << 8);            // 2048 float4
            float4 v = __ldg(&w4[idx]);
            v.x *= 2.5f; v.y *= 2.5f; v.z *= 2.5f; v.w *= 2.5f;
            int row = idx >> 4, c4 = idx & 15;
            uint32_t off = (uint32_t)row * ROWB + c4 * 8;
            __half h0 = __float2half_rn(v.x);
            __half h1 = __float2half_rn(v.y);
            __half h2 = __float2half_rn(v.z);
            __half h3 = __float2half_rn(v.w);
            uint2 hi;
            hi.x = pack_h2(h0, h1); hi.y = pack_h2(h2, h3);
            *reinterpret_cast<uint2*>(smem + SMEM_W_HI + off) = hi;
        }
    }
    __syncthreads();

    if (tid >= 128) {
        // ==================== PRODUCERS ====================
        const int pt   = tid - 128;
        const int lane = pt & 31;
        const int pw   = pt >> 5;                // heads [32pw, 32pw+32)
        const int j    = lane >> 3;

        const uint32_t a_off = (uint32_t)(((j & 1) * 8 + (lane & 7)) * WSTR + ((j >> 1) * 8)) * 2;
        const uint32_t b_off = (uint32_t)(((j >> 1) * 8 + (lane & 7)) * WSTR + ((j & 1) * 8)) * 2;

        // hoist W_hi fragments into registers (ff ring aliases W_hi after)
        uint32_t Ahi[2][4][4];
        {
            const uint32_t aW_hi = sb + SMEM_W_HI + (uint32_t)(pw * 32) * ROWB + a_off;
#pragma unroll
            for (int mt = 0; mt < 2; ++mt)
#pragma unroll
                for (int ks = 0; ks < 4; ++ks)
                    ldm_x4(Ahi[mt][ks], aW_hi + (uint32_t)mt * 16 * ROWB + ks * 32);
        }
        asm volatile("bar.sync 13, 128;" ::: "memory");

        // bias' = 2.5*b - 1.5 folded into accumulator init
        const int r0 = lane >> 2;
        const int c0 = 2 * (lane & 3);
        float bias0[2], bias1[2];
#pragma unroll
        for (int mt = 0; mt < 2; ++mt) {
            bias0[mt] = fmaf(__ldg(&bvec[pw * 32 + mt * 16 + r0]), 2.5f, -1.5f);
            bias1[mt] = fmaf(__ldg(&bvec[pw * 32 + mt * 16 + r0 + 8]), 2.5f, -1.5f);
        }

        for (int i = 0; i < N_TILES; ++i) {
            const int s = i & 1;
            BAR_SYNC(5 + s);                     // wait x tile i converted

            bool ff_waited = false;
#pragma unroll
            for (int hf = 0; hf < 2; ++hf) {     // two 32-step halves
                float d[2][4][4];
#pragma unroll
                for (int mt = 0; mt < 2; ++mt)
#pragma unroll
                    for (int nt = 0; nt < 4; ++nt) {
                        d[mt][nt][0] = bias0[mt]; d[mt][nt][1] = bias0[mt];
                        d[mt][nt][2] = bias1[mt]; d[mt][nt][3] = bias1[mt];
                    }
                const uint32_t bX_hi = sb + XBUF(s) + (uint32_t)(hf * 32) * ROWB + b_off;
                const uint32_t bX_lo = bX_hi + XLO;
#pragma unroll
                for (int ks = 0; ks < 4; ++ks) {
                    uint32_t bh[2][4], bl[2][4];
                    ldm_x4(bh[0], bX_hi + ks * 32);
                    ldm_x4(bh[1], bX_hi + 16 * ROWB + ks * 32);
                    ldm_x4(bl[0], bX_lo + ks * 32);
                    ldm_x4(bl[1], bX_lo + 16 * ROWB + ks * 32);
#pragma unroll
                    for (int mt = 0; mt < 2; ++mt)
#pragma unroll
                        for (int nt = 0; nt < 4; ++nt) {
                            const uint32_t* bhp = &bh[nt >> 1][(nt & 1) * 2];
                            const uint32_t* blp = &bl[nt >> 1][(nt & 1) * 2];
                            mma_f16(d[mt][nt], Ahi[mt][ks], bhp);   // wh*xh
                            mma_f16(d[mt][nt], Ahi[mt][ks], blp);   // wh*xl
                        }
                }
                if (!ff_waited) {
                    if (i >= 2) BAR_SYNC(3 + s); // wait ff slot free (once)
                    ff_waited = true;
                }
                // store half hf, layout [t][h] stride 132 (conflict-free)
                {
                    float* ffp = reinterpret_cast<float*>(smem + FFB(s))
                                 + (size_t)(hf * 32) * FF_STR;
                    const int baser = pw * 32 + r0;
#pragma unroll
                    for (int mt = 0; mt < 2; ++mt) {
                        const int row = baser + mt * 16;
#pragma unroll
                        for (int nt = 0; nt < 4; ++nt) {
                            const int col = nt * 8 + c0;
                            ffp[col * FF_STR + row]           = d[mt][nt][0];
                            ffp[(col + 1) * FF_STR + row]     = d[mt][nt][1];
                            ffp[col * FF_STR + row + 8]       = d[mt][nt][2];
                            ffp[(col + 1) * FF_STR + row + 8] = d[mt][nt][3];
                        }
                    }
                }
            }
            BAR_ARRIVE(7 + s);                   // x slot free (all LDSM done)
            BAR_ARRIVE(1 + s);                   // ff tile ready
        }
    } else {
        // ==================== CONSUMERS (scan + x feed) ====================
        const int h  = tid;
        const int ct = tid;
        float* outp = out + (size_t)b * T_DIM * H_DIM + h;

        // prologue: convert x tile 0 into slot 0; prefetch tile 1 regs
        float4 xr[8];
        {
            const float4* x4 = reinterpret_cast<const float4*>(xb);
#pragma unroll
            for (int q = 0; q < 8; ++q) xr[q] = __ldg(&x4[ct + (q << 7)]);
            convert_to_slot(smem, 0, ct, xr);
            BAR_ARRIVE(5 + 0);
            x4 = reinterpret_cast<const float4*>(xb + (size_t)TILE_T * K_DIM);
#pragma unroll
            for (int q = 0; q < 8; ++q) xr[q] = __ldg(&x4[ct + (q << 7)]);
        }

        // scan state: z = 0.9*y_{-1} - 1.25*th_{-1} = -1.0 (mem=0, spk=0)
        float z = -1.0f;

        for (int i = 0; i < N_TILES; ++i) {
            const int s = i & 1;

            // convert x(i+1) FIRST and publish — producers never wait on scan
            if (i + 1 < N_TILES) {
                const int sn = (i + 1) & 1;
                if (i + 1 >= 2) BAR_SYNC(7 + sn);    // x slot free
                convert_to_slot(smem, sn, ct, xr);
                BAR_ARRIVE(5 + sn);                  // x tile i+1 ready
            }
            // prefetch x(i+2) regs
            if (i + 2 < N_TILES) {
                const float4* x4 = reinterpret_cast<const float4*>(
                    xb + (size_t)(i + 2) * TILE_T * K_DIM);
#pragma unroll
                for (int q = 0; q < 8; ++q) xr[q] = __ldg(&x4[ct + (q << 7)]);
            }

            BAR_SYNC(1 + s);                     // wait ff tile i
            const float* fp = reinterpret_cast<const float*>(smem + FFB(s)) + h;
            float* po = outp + (size_t)i * TILE_T * H_DIM;

            // half A: LDS 32, scan 32
            float g[32];
#pragma unroll
            for (int t = 0; t < 32; ++t) g[t] = fp[t * FF_STR];
            float y = z + g[0];
#pragma unroll
            for (int t = 0; t < 32; ++t) {
                float th = tanhf_approx(y);          // MUFU (critical path)
                float gn = (t < 31) ? g[t + 1] : 0.0f;
                float a  = fmaf(0.9f, y, gn);
                y = fmaf(th, -1.25f, a);
                float spk = fmaf(th, 0.5f, 0.5f);
                po[(size_t)t * H_DIM] = spk;
            }
            z = y;

            // half B: LDS 32, free slot, scan 32
#pragma unroll
            for (int t = 0; t < 32; ++t) g[t] = fp[(t + 32) * FF_STR];
            BAR_ARRIVE(3 + s);                   // ff slot free
            y = z + g[0];
#pragma unroll
            for (int t = 0; t < 32; ++t) {
                float th = tanhf_approx(y);
                float gn = (t < 31) ? g[t + 1] : 0.0f;
                float a  = fmaf(0.9f, y, gn);
                y = fmaf(th, -1.25f, a);
                float spk = fmaf(th, 0.5f, 0.5f);
                po[(size_t)(t + 32) * H_DIM] = spk;
            }
            z = y;
        }
    }
}

// ============================================================================
// Launch. Inputs: x [256,2048,64] f32, W [128,64] f32, b [128] f32 -> out f32
// ============================================================================
extern "C" void kernel_launch(void* const* d_in, const int* in_sizes, int n_in,
                              void* d_out, int out_size) {
    const float* x = (const float*)d_in[0];
    const float* W = (const float*)d_in[1];
    const float* b = (const float*)d_in[2];
    float* out = (float*)d_out;

    cudaFuncSetAttribute(snn_encoder_kernel,
                         cudaFuncAttributeMaxDynamicSharedMemorySize, SMEM_TOTAL);
    snn_encoder_kernel<<<B_DIM, 256, SMEM_TOTAL>>>(x, W, b, out);
}

// round 16
// speedup vs baseline: 1.2603x; 1.1703x over previous
#include <cuda_runtime.h>
#include <cuda_fp16.h>
#include <cstdint>

// ============================================================================
// Problem constants
// ============================================================================
#define B_DIM   256
#define T_DIM   2048
#define K_DIM   64
#define H_DIM   128
#define TILE_T  32
#define N_TILES (T_DIM / TILE_T)   // 64

// Scan: y_t = 0.9*y_{t-1} - 1.25*th_{t-1} + g_t, th = tanh(y), spk = .5th+.5
// g = 2.5*ff - 1.5  (2.5 folded into W, bias' = 2.5b - 1.5)
// GEMM: 2-term fp16 split  ff ~= wh*xh + wh*xl,  xl = fp16(x - xh)

// ============================================================================
// SMEM layout (bytes) — 101376 total (2 CTAs/SM)
//   [0, 27648)        x ring: 3 slots x 9216 (fp16 hi 4608 + fp16 lo 4608)
//   [27648, 101376)   ff ring: 4 slots x 18432 ([t][h] stride 132 floats —
//                     only 16896 used per slot; 18432 keeps W_hi alias room)
//   W_hi (init only) aliases ff region at 27648 (128 x 144 B = 18432).
// ============================================================================
#define WSTR      72
#define ROWB      144
#define XBUF(s)   ((s) * 9216)
#define SMEM_FF   27648
#define FFB(s)    (SMEM_FF + (s) * 18432)
#define FF_STR    132
#define SMEM_W_HI 27648
#define SMEM_TOTAL 101376

// Named barriers (256 threads = 128 producers + 128 consumers):
//   FFREADY(s)=1+s (s 0..3), FFFREE(s)=5+s, XREADY(s)=9+s (s 0..2),
//   XFREE(s)=12+s, 15 = producer-only (128) W_hi hoist guard
#define BAR_SYNC(id)   asm volatile("bar.sync %0, 256;"   :: "r"(id) : "memory")
#define BAR_ARRIVE(id) asm volatile("bar.arrive %0, 256;" :: "r"(id) : "memory")

// ============================================================================
// Helpers
// ============================================================================
__device__ __forceinline__ uint32_t smem_to_u32(const void* p) {
    uint32_t a;
    asm("{ .reg .u64 t; cvta.to.shared.u64 t, %1; cvt.u32.u64 %0, t; }"
        : "=r"(a) : "l"(p));
    return a;
}
__device__ __forceinline__ float tanhf_approx(float x) {
    float y; asm("tanh.approx.f32 %0, %1;" : "=f"(y) : "f"(x)); return y;
}
__device__ __forceinline__ void ldm_x4(uint32_t* r, uint32_t addr) {
    asm volatile("ldmatrix.sync.aligned.m8n8.x4.shared.b16 {%0,%1,%2,%3}, [%4];"
        : "=r"(r[0]), "=r"(r[1]), "=r"(r[2]), "=r"(r[3]) : "r"(addr));
}
__device__ __forceinline__ void mma_f16(float* d, const uint32_t* a, const uint32_t* b) {
    asm volatile(
        "mma.sync.aligned.m16n8k16.row.col.f32.f16.f16.f32 "
        "{%0,%1,%2,%3},{%4,%5,%6,%7},{%8,%9},{%0,%1,%2,%3};"
        : "+f"(d[0]), "+f"(d[1]), "+f"(d[2]), "+f"(d[3])
        : "r"(a[0]), "r"(a[1]), "r"(a[2]), "r"(a[3]), "r"(b[0]), "r"(b[1]));
}
// bitcast __half2 -> uint32 (no such intrinsic in headers)
__device__ __forceinline__ uint32_t h2_as_u32(__half2 h) {
    union { __half2 h2; uint32_t u; } cvt;
    cvt.h2 = h;
    return cvt.u;
}
// packed 2-term fp16 split: hi2 = f16x2(v01), lo2 = f16x2(v01 - f32(hi2))
__device__ __forceinline__ void cvt_pack_f16_fast(float4 v, uint2& hi, uint2& lo) {
    __half2 h01 = __floats2half2_rn(v.x, v.y);       // 1x F2FP.PACK
    __half2 h23 = __floats2half2_rn(v.z, v.w);
    float2 f01 = __half22float2(h01);                // back-convert
    float2 f23 = __half22float2(h23);
    __half2 l01 = __floats2half2_rn(v.x - f01.x, v.y - f01.y);
    __half2 l23 = __floats2half2_rn(v.z - f23.x, v.w - f23.y);
    hi.x = h2_as_u32(h01); hi.y = h2_as_u32(h23);
    lo.x = h2_as_u32(l01); lo.y = h2_as_u32(l23);
}
// consumer-side: convert xr regs -> x ring slot s (hi + lo fp16 planes)
__device__ __forceinline__ void convert_to_slot(char* smem, int s, int ct,
                                                const float4* xr) {
#pragma unroll
    for (int q = 0; q < 4; ++q) {
        int idx = ct + (q << 7);
        int row = idx >> 4, c4 = idx & 15;
        uint32_t off = (uint32_t)row * ROWB + c4 * 8;
        uint2 hi, lo; cvt_pack_f16_fast(xr[q], hi, lo);
        *reinterpret_cast<uint2*>(smem + XBUF(s) + off)        = hi;
        *reinterpret_cast<uint2*>(smem + XBUF(s) + 4608 + off) = lo;
    }
}

// ============================================================================
// Warp-specialized kernel (R12 skeleton + packed cvt + 4-slot ff ring).
//   tid 0..127  : consumers — tanh scan (thread = head) + x load/convert
//                 (convert + x-READY published BEFORE the scan)
//   tid 128..255: producers — 2-term fp16 GEMM (A in regs, 64 HMMA/tile)
// ============================================================================
__global__ void __launch_bounds__(256, 2)
snn_encoder_kernel(const float* __restrict__ x, const float* __restrict__ W,
                   const float* __restrict__ bvec, float* __restrict__ out) {
    extern __shared__ char smem[];
    const uint32_t sb = smem_to_u32(smem);
    const int tid = threadIdx.x;
    const int b   = blockIdx.x;
    const float* xb = x + (size_t)b * T_DIM * K_DIM;

    // ---- Cooperative W convert: (2.5*W) fp32 -> fp16 hi only (aliases ff)
    {
        const float4* w4 = reinterpret_cast<const float4*>(W);
#pragma unroll
        for (int q = 0; q < 8; ++q) {
            int idx = tid + (q << 8);            // 2048 float4
            float4 v = __ldg(&w4[idx]);
            v.x *= 2.5f; v.y *= 2.5f; v.z *= 2.5f; v.w *= 2.5f;
            int row = idx >> 4, c4 = idx & 15;
            uint32_t off = (uint32_t)row * ROWB + c4 * 8;
            __half2 h01 = __floats2half2_rn(v.x, v.y);
            __half2 h23 = __floats2half2_rn(v.z, v.w);
            uint2 hi;
            hi.x = h2_as_u32(h01); hi.y = h2_as_u32(h23);
            *reinterpret_cast<uint2*>(smem + SMEM_W_HI + off) = hi;
        }
    }
    __syncthreads();

    if (tid >= 128) {
        // ==================== PRODUCERS ====================
        const int pt   = tid - 128;
        const int lane = pt & 31;
        const int pw   = pt >> 5;                // heads [32pw, 32pw+32)
        const int j    = lane >> 3;

        const uint32_t a_off = (uint32_t)(((j & 1) * 8 + (lane & 7)) * WSTR + ((j >> 1) * 8)) * 2;
        const uint32_t b_off = (uint32_t)(((j >> 1) * 8 + (lane & 7)) * WSTR + ((j & 1) * 8)) * 2;

        // hoist W_hi fragments into registers (ff ring aliases W_hi after)
        uint32_t Ahi[2][4][4];
        {
            const uint32_t aW_hi = sb + SMEM_W_HI + (uint32_t)(pw * 32) * ROWB + a_off;
#pragma unroll
            for (int mt = 0; mt < 2; ++mt)
#pragma unroll
                for (int ks = 0; ks < 4; ++ks)
                    ldm_x4(Ahi[mt][ks], aW_hi + (uint32_t)mt * 16 * ROWB + ks * 32);
        }
        asm volatile("bar.sync 15, 128;" ::: "memory");

        // bias' = 2.5*b - 1.5 folded into accumulator init
        const int r0 = lane >> 2;
        const int c0 = 2 * (lane & 3);
        float bias0[2], bias1[2];
#pragma unroll
        for (int mt = 0; mt < 2; ++mt) {
            bias0[mt] = fmaf(__ldg(&bvec[pw * 32 + mt * 16 + r0]), 2.5f, -1.5f);
            bias1[mt] = fmaf(__ldg(&bvec[pw * 32 + mt * 16 + r0 + 8]), 2.5f, -1.5f);
        }

        int sx = 0, sf = 0;
        for (int i = 0; i < N_TILES; ++i) {
            BAR_SYNC(9 + sx);                    // wait x tile i converted

            float d[2][4][4];
#pragma unroll
            for (int mt = 0; mt < 2; ++mt)
#pragma unroll
                for (int nt = 0; nt < 4; ++nt) {
                    d[mt][nt][0] = bias0[mt]; d[mt][nt][1] = bias0[mt];
                    d[mt][nt][2] = bias1[mt]; d[mt][nt][3] = bias1[mt];
                }
            const uint32_t bX_hi = sb + XBUF(sx) + b_off;
            const uint32_t bX_lo = bX_hi + 4608;
#pragma unroll
            for (int ks = 0; ks < 4; ++ks) {
                uint32_t bh[2][4], bl[2][4];
                ldm_x4(bh[0], bX_hi + ks * 32);
                ldm_x4(bh[1], bX_hi + 16 * ROWB + ks * 32);
                ldm_x4(bl[0], bX_lo + ks * 32);
                ldm_x4(bl[1], bX_lo + 16 * ROWB + ks * 32);
#pragma unroll
                for (int mt = 0; mt < 2; ++mt)
#pragma unroll
                    for (int nt = 0; nt < 4; ++nt) {
                        const uint32_t* bhp = &bh[nt >> 1][(nt & 1) * 2];
                        const uint32_t* blp = &bl[nt >> 1][(nt & 1) * 2];
                        mma_f16(d[mt][nt], Ahi[mt][ks], bhp);   // wh * xh
                        mma_f16(d[mt][nt], Ahi[mt][ks], blp);   // wh * xl
                    }
            }
            BAR_ARRIVE(12 + sx);                 // x slot free (LDSM done)

            if (i >= 4) BAR_SYNC(5 + sf);        // wait ff slot free (ring 4)

            // store ff tile, layout [t][h], stride 132 (conflict-free)
            {
                float* ffp = reinterpret_cast<float*>(smem + FFB(sf));
                const int baser = pw * 32 + r0;
#pragma unroll
                for (int mt = 0; mt < 2; ++mt) {
                    const int row = baser + mt * 16;
#pragma unroll
                    for (int nt = 0; nt < 4; ++nt) {
                        const int col = nt * 8 + c0;
                        ffp[col * FF_STR + row]           = d[mt][nt][0];
                        ffp[(col + 1) * FF_STR + row]     = d[mt][nt][1];
                        ffp[col * FF_STR + row + 8]       = d[mt][nt][2];
                        ffp[(col + 1) * FF_STR + row + 8] = d[mt][nt][3];
                    }
                }
            }
            BAR_ARRIVE(1 + sf);                  // ff tile ready

            if (++sx == 3) sx = 0;
            if (++sf == 4) sf = 0;
        }
    } else {
        // ==================== CONSUMERS (scan + x feed) ====================
        const int h  = tid;
        const int ct = tid;
        float* outp = out + (size_t)b * T_DIM * H_DIM + h;

        // prologue: convert x tiles 0,1 into slots 0,1; prefetch tile 2
        float4 xr[4];
        {
            const float4* x4 = reinterpret_cast<const float4*>(xb);
#pragma unroll
            for (int q = 0; q < 4; ++q) xr[q] = __ldg(&x4[ct + (q << 7)]);
            convert_to_slot(smem, 0, ct, xr);
            BAR_ARRIVE(9 + 0);
            x4 = reinterpret_cast<const float4*>(xb + (size_t)TILE_T * K_DIM);
#pragma unroll
            for (int q = 0; q < 4; ++q) xr[q] = __ldg(&x4[ct + (q << 7)]);
            convert_to_slot(smem, 1, ct, xr);
            BAR_ARRIVE(9 + 1);
            x4 = reinterpret_cast<const float4*>(xb + (size_t)2 * TILE_T * K_DIM);
#pragma unroll
            for (int q = 0; q < 4; ++q) xr[q] = __ldg(&x4[ct + (q << 7)]);
        }

        // scan state: z = 0.9*y_{-1} - 1.25*th_{-1} = -1.0 (mem=0, spk=0)
        float z = -1.0f;
        int sf = 0, sx = 2;                      // next convert slot = tile 2

        for (int i = 0; i < N_TILES; ++i) {
            // convert tile i+2 FIRST (publish before scanning), prefetch i+3
            if (i + 2 < N_TILES) {
                if (i + 2 >= 3) BAR_SYNC(12 + sx);
                convert_to_slot(smem, sx, ct, xr);
                BAR_ARRIVE(9 + sx);
                if (++sx == 3) sx = 0;
            }
            if (i + 3 < N_TILES) {
                const float4* x4 = reinterpret_cast<const float4*>(
                    xb + (size_t)(i + 3) * TILE_T * K_DIM);
#pragma unroll
                for (int q = 0; q < 4; ++q) xr[q] = __ldg(&x4[ct + (q << 7)]);
            }

            BAR_SYNC(1 + sf);                    // wait ff tile i
            const float* fp = reinterpret_cast<const float*>(smem + FFB(sf)) + h;
            float g[TILE_T];
#pragma unroll
            for (int t = 0; t < TILE_T; ++t) g[t] = fp[t * FF_STR];
            BAR_ARRIVE(5 + sf);                  // free ff slot immediately
            if (++sf == 4) sf = 0;

            float* po = outp + (size_t)i * TILE_T * H_DIM;
            float y = z + g[0];
#pragma unroll
            for (int t = 0; t < TILE_T; ++t) {
                float th = tanhf_approx(y);          // MUFU (critical path)
                float gn = (t < TILE_T - 1) ? g[t + 1] : 0.0f;
                float a  = fmaf(0.9f, y, gn);        // parallel with tanh
                y = fmaf(th, -1.25f, a);             // y_{t+1} (or z at t=31)
                float spk = fmaf(th, 0.5f, 0.5f);    // off critical path
                po[(size_t)t * H_DIM] = spk;
            }
            z = y;                               // carry partial to next tile
        }
    }
}

// ============================================================================
// Launch. Inputs: x [256,2048,64] f32, W [128,64] f32, b [128] f32 -> out f32
// ============================================================================
extern "C" void kernel_launch(void* const* d_in, const int* in_sizes, int n_in,
                              void* d_out, int out_size) {
    const float* x = (const float*)d_in[0];
    const float* W = (const float*)d_in[1];
    const float* b = (const float*)d_in[2];
    float* out = (float*)d_out;

    cudaFuncSetAttribute(snn_encoder_kernel,
                         cudaFuncAttributeMaxDynamicSharedMemorySize, SMEM_TOTAL);
    snn_encoder_kernel<<<B_DIM, 256, SMEM_TOTAL>>>(x, W, b, out);
}